// round 11
// baseline (speedup 1.0000x reference)
#include <cuda_runtime.h>
#include <cuda_bf16.h>
#include <cstdint>

// ---------------------------------------------------------------------------
// RecurrentGraphNeuralNet v10: CSR-based aggregation (no float atomics):
//   hist -> scan -> reorder(src by dst) -> per-node register accumulation
// Update kernel: HMMA bf16 split-precision (3 passes), cp.async weight image.
// ---------------------------------------------------------------------------

#define MAXN 100000
#define MAXE 1664000

__device__ float g_mean[(long long)MAXN * 64];
__device__ int   g_count[MAXN];
__device__ int   g_start[MAXN];
__device__ int   g_fill[MAXN];
__device__ int   g_srcs[MAXE];
__device__ int   g_is64;

// Weight image: [Whi 17408][Wlo 17408][Wph 4608][Wpl 4608][bs 256][bps 128]
#define IMG_WHI 0
#define IMG_WLO 17408
#define IMG_WPH 34816
#define IMG_WPL 39424
#define IMG_BS  44032
#define IMG_BPS 44288
#define IMG_BYTES 44416
__device__ __align__(128) unsigned char g_wimg[IMG_BYTES];

// ---------------------------------------------------------------------------
__device__ __forceinline__ uint32_t smem_u32(const void* p) {
    uint32_t a;
    asm("{ .reg .u64 t; cvta.to.shared.u64 t, %1; cvt.u32.u64 %0, t; }"
        : "=r"(a) : "l"(p));
    return a;
}
__device__ __forceinline__ void ldsm_x4(uint32_t addr, uint32_t r[4]) {
    asm volatile("ldmatrix.sync.aligned.m8n8.x4.shared.b16 {%0,%1,%2,%3}, [%4];"
        : "=r"(r[0]), "=r"(r[1]), "=r"(r[2]), "=r"(r[3]) : "r"(addr));
}
__device__ __forceinline__ void mma16816(float d[4], const uint32_t a[4],
                                         const uint32_t b[2]) {
    asm volatile(
        "mma.sync.aligned.m16n8k16.row.col.f32.bf16.bf16.f32 "
        "{%0,%1,%2,%3}, {%4,%5,%6,%7}, {%8,%9}, {%0,%1,%2,%3};"
        : "+f"(d[0]), "+f"(d[1]), "+f"(d[2]), "+f"(d[3])
        : "r"(a[0]), "r"(a[1]), "r"(a[2]), "r"(a[3]), "r"(b[0]), "r"(b[1]));
}
__device__ __forceinline__ void cp_async16(uint32_t dst, const void* src) {
    asm volatile("cp.async.cg.shared.global [%0], [%1], 16;"
                 :: "r"(dst), "l"(src) : "memory");
}
__device__ __forceinline__ uint32_t pack_bf2(float lo, float hi) {
    __nv_bfloat162 h = __floats2bfloat162_rn(lo, hi);
    return *reinterpret_cast<uint32_t*>(&h);
}
__device__ __forceinline__ float bf_lo(uint32_t w) {
    __nv_bfloat16 h = *reinterpret_cast<__nv_bfloat16*>(&w);
    return __bfloat162float(h);
}
__device__ __forceinline__ float bf_hi(uint32_t w) {
    uint32_t s = w >> 16;
    __nv_bfloat16 h = *reinterpret_cast<__nv_bfloat16*>(&s);
    return __bfloat162float(h);
}

// SMEM layout (bytes)
#define SO_AHI   0
#define SO_ALO   34816
#define SO_WIMG  69632
#define SO_WHI   (SO_WIMG + IMG_WHI)
#define SO_WLO   (SO_WIMG + IMG_WLO)
#define SO_WPH   (SO_WIMG + IMG_WPH)
#define SO_WPL   (SO_WIMG + IMG_WPL)
#define SO_BS    (SO_WIMG + IMG_BS)
#define SO_BPS   (SO_WIMG + IMG_BPS)
#define SMEM_BYTES (SO_WIMG + IMG_BYTES)   // 114048

// ---------------------------------------------------------------------------
__global__ void detect_idx_kernel(const void* ei, int E, int N) {
    if (blockIdx.x == 0 && threadIdx.x == 0) {
        const long long* p = (const long long*)ei;
        int is64 = 1;
        #pragma unroll
        for (int i = 0; i < 8; i++) {
            long long v = p[i];
            if (v < 0 || v >= (long long)N) { is64 = 0; break; }
        }
        g_is64 = is64;
    }
}

__global__ void zero_count_kernel(int n) {
    int i = blockIdx.x * blockDim.x + threadIdx.x;
    if (i < n) g_count[i] = 0;
}

// histogram of dst
__global__ __launch_bounds__(256) void hist_kernel(
    const void* __restrict__ ei_raw, int E)
{
    int e = blockIdx.x * blockDim.x + threadIdx.x;
    if (e >= E) return;
    int d;
    if (g_is64) d = (int)((const long long*)ei_raw)[(long long)E + e];
    else        d = ((const int*)ei_raw)[E + e];
    atomicAdd(&g_count[d], 1);
}

// one-block chunked exclusive scan: g_start/g_fill
__global__ void scan_kernel(int N) {
    __shared__ int psum[1024];
    int t = threadIdx.x;
    int chunk = (N + 1023) / 1024;
    int beg = t * chunk;
    int end = min(beg + chunk, N);
    int s = 0;
    for (int i = beg; i < end; i++) s += g_count[i];
    psum[t] = s;
    __syncthreads();
    #pragma unroll
    for (int off = 1; off < 1024; off <<= 1) {
        int v = (t >= off) ? psum[t - off] : 0;
        __syncthreads();
        psum[t] += v;
        __syncthreads();
    }
    int run = psum[t] - s;     // exclusive prefix at chunk start
    for (int i = beg; i < end; i++) {
        g_start[i] = run;
        g_fill[i]  = run;
        run += g_count[i];
    }
}

// bucket srcs by dst
__global__ __launch_bounds__(256) void reorder_kernel(
    const void* __restrict__ ei_raw, int E)
{
    int e = blockIdx.x * blockDim.x + threadIdx.x;
    if (e >= E) return;
    int s, d;
    if (g_is64) {
        const long long* ei = (const long long*)ei_raw;
        s = (int)ei[e];
        d = (int)ei[(long long)E + e];
    } else {
        const int* ei = (const int*)ei_raw;
        s = ei[e];
        d = ei[E + e];
    }
    int pos = atomicAdd(&g_fill[d], 1);
    g_srcs[pos] = s;
}

// per-node aggregation: 16 threads/node, register accumulation, writes mean
__global__ __launch_bounds__(256) void aggregate_kernel(
    const float* __restrict__ x, int N)
{
    int n = blockIdx.x * 16 + (threadIdx.x >> 4);
    if (n >= N) return;
    const int f4 = (threadIdx.x & 15) * 4;

    const int start = g_start[n];
    const int cnt   = g_count[n];
    const int* srcs = g_srcs + start;

    float4 acc = make_float4(0.f, 0.f, 0.f, 0.f);
    int j = 0;
    for (; j + 4 <= cnt; j += 4) {
        int s0 = srcs[j], s1 = srcs[j + 1], s2 = srcs[j + 2], s3 = srcs[j + 3];
        float4 v0 = *reinterpret_cast<const float4*>(x + (long long)s0 * 64 + f4);
        float4 v1 = *reinterpret_cast<const float4*>(x + (long long)s1 * 64 + f4);
        float4 v2 = *reinterpret_cast<const float4*>(x + (long long)s2 * 64 + f4);
        float4 v3 = *reinterpret_cast<const float4*>(x + (long long)s3 * 64 + f4);
        acc.x += v0.x; acc.y += v0.y; acc.z += v0.z; acc.w += v0.w;
        acc.x += v1.x; acc.y += v1.y; acc.z += v1.z; acc.w += v1.w;
        acc.x += v2.x; acc.y += v2.y; acc.z += v2.z; acc.w += v2.w;
        acc.x += v3.x; acc.y += v3.y; acc.z += v3.z; acc.w += v3.w;
    }
    for (; j < cnt; j++) {
        int s0 = srcs[j];
        float4 v0 = *reinterpret_cast<const float4*>(x + (long long)s0 * 64 + f4);
        acc.x += v0.x; acc.y += v0.y; acc.z += v0.z; acc.w += v0.w;
    }
    float inv = 1.0f / (float)max(cnt, 1);
    acc.x *= inv; acc.y *= inv; acc.z *= inv; acc.w *= inv;
    *reinterpret_cast<float4*>(g_mean + (long long)n * 64 + f4) = acc;
}

// Build the hi/lo-split, transposed, ldmatrix-ready weight image (once).
__global__ void setup_weights_kernel(
    const float* __restrict__ W, const float* __restrict__ Bm,
    const float* __restrict__ Wp, const float* __restrict__ b,
    const float* __restrict__ bp)
{
    int i = blockIdx.x * blockDim.x + threadIdx.x;
    if (i < 8192) {
        int n = i & 63, k = i >> 6;
        float wv = (k < 64) ? W[k * 64 + n] : Bm[(k - 64) * 64 + n];
        __nv_bfloat16 whi = __float2bfloat16(wv);
        __nv_bfloat16 wlo = __float2bfloat16(wv - __bfloat162float(whi));
        uint32_t off = (uint32_t)(n * 136 + k) * 2;
        *reinterpret_cast<__nv_bfloat16*>(g_wimg + IMG_WHI + off) = whi;
        *reinterpret_cast<__nv_bfloat16*>(g_wimg + IMG_WLO + off) = wlo;
    } else if (i < 10240) {
        int j = i - 8192;
        int p = j & 31, k = j >> 5;
        float wv = Wp[k * 32 + p];
        __nv_bfloat16 whi = __float2bfloat16(wv);
        __nv_bfloat16 wlo = __float2bfloat16(wv - __bfloat162float(whi));
        uint32_t off = (uint32_t)(p * 72 + k) * 2;
        *reinterpret_cast<__nv_bfloat16*>(g_wimg + IMG_WPH + off) = whi;
        *reinterpret_cast<__nv_bfloat16*>(g_wimg + IMG_WPL + off) = wlo;
    } else if (i < 10304) {
        int j = i - 10240;
        *reinterpret_cast<float*>(g_wimg + IMG_BS + j * 4) = b[j];
    } else if (i < 10336) {
        int j = i - 10304;
        *reinterpret_cast<float*>(g_wimg + IMG_BPS + j * 4) = bp[j];
    }
}

// ---------------------------------------------------------------------------
// Update: 128 nodes/block, 256 threads, HMMA 3-pass (mean precomputed).
__global__ __launch_bounds__(256, 2) void update_kernel(
    const float* __restrict__ u, float* __restrict__ out, int N)
{
    extern __shared__ char smem[];
    const uint32_t sb = smem_u32(smem);
    const int t = threadIdx.x;
    const int l = t & 31;
    const int w = t >> 5;
    const int base = blockIdx.x * 128;

    float* bs  = (float*)(smem + SO_BS);
    float* bps = (float*)(smem + SO_BPS);

    for (int i = t; i < IMG_BYTES / 16; i += 256)
        cp_async16(sb + SO_WIMG + i * 16, g_wimg + i * 16);
    asm volatile("cp.async.commit_group;" ::: "memory");

    #pragma unroll
    for (int it = 0; it < 16; it++) {
        int node = w + it * 8;
        int gn = base + node;
        int ch = l;
        float4 v = make_float4(0.f, 0.f, 0.f, 0.f);
        if (gn < N) {
            if (ch < 16)
                v = *reinterpret_cast<const float4*>(g_mean + (long long)gn * 64 + ch * 4);
            else
                v = *reinterpret_cast<const float4*>(u + (long long)gn * 64 + (ch - 16) * 4);
        }
        uint32_t h01 = pack_bf2(v.x, v.y);
        uint32_t h23 = pack_bf2(v.z, v.w);
        uint32_t l01 = pack_bf2(v.x - bf_lo(h01), v.y - bf_hi(h01));
        uint32_t l23 = pack_bf2(v.z - bf_lo(h23), v.w - bf_hi(h23));
        uint32_t off = (uint32_t)(node * 136 + ch * 4) * 2;
        *reinterpret_cast<uint2*>(smem + SO_AHI + off) = make_uint2(h01, h23);
        *reinterpret_cast<uint2*>(smem + SO_ALO + off) = make_uint2(l01, l23);
    }

    asm volatile("cp.async.wait_group 0;" ::: "memory");
    __syncthreads();

    float acc[8][4];
    #pragma unroll
    for (int n = 0; n < 8; n++)
        #pragma unroll
        for (int q = 0; q < 4; q++) acc[n][q] = 0.f;

    const uint32_t a_off = (uint32_t)((w * 16 + (l & 15)) * 136 + (l >> 4) * 8) * 2;
    const uint32_t b_off = (uint32_t)(((l & 7) + ((l >> 4) & 1) * 8) * 136 +
                                      ((l >> 3) & 1) * 8) * 2;

    auto gemm_pass = [&](uint32_t abase, uint32_t bbase) {
        #pragma unroll
        for (int kt = 0; kt < 8; kt++) {
            uint32_t af[4];
            ldsm_x4(abase + a_off + kt * 32, af);
            #pragma unroll
            for (int np = 0; np < 4; np++) {
                uint32_t bq[4];
                ldsm_x4(bbase + b_off + np * (16 * 136 * 2) + kt * 32, bq);
                mma16816(acc[2 * np],     af, bq);
                mma16816(acc[2 * np + 1], af, bq + 2);
            }
        }
    };
    gemm_pass(sb + SO_AHI, sb + SO_WHI);
    gemm_pass(sb + SO_AHI, sb + SO_WLO);
    gemm_pass(sb + SO_ALO, sb + SO_WHI);

    uint32_t xh[8][2], xl[8][2];
    {
        int r0 = base + w * 16 + (l >> 2);
        #pragma unroll
        for (int n = 0; n < 8; n++) {
            int c = n * 8 + (l & 3) * 2;
            float b0 = bs[c], b1 = bs[c + 1];
            float d0 = fmaxf(acc[n][0] + b0, 0.f);
            float d1 = fmaxf(acc[n][1] + b1, 0.f);
            float d2 = fmaxf(acc[n][2] + b0, 0.f);
            float d3 = fmaxf(acc[n][3] + b1, 0.f);
            uint32_t h01 = pack_bf2(d0, d1);
            uint32_t h23 = pack_bf2(d2, d3);
            xh[n][0] = h01;
            xh[n][1] = h23;
            xl[n][0] = pack_bf2(d0 - bf_lo(h01), d1 - bf_hi(h01));
            xl[n][1] = pack_bf2(d2 - bf_lo(h23), d3 - bf_hi(h23));
            if (r0 < N)
                *reinterpret_cast<float2*>(out + (long long)r0 * 64 + c) =
                    make_float2(d0, d1);
            if (r0 + 8 < N)
                *reinterpret_cast<float2*>(out + (long long)(r0 + 8) * 64 + c) =
                    make_float2(d2, d3);
        }
    }

    float y[4][4];
    #pragma unroll
    for (int nt = 0; nt < 4; nt++)
        #pragma unroll
        for (int q = 0; q < 4; q++) y[nt][q] = 0.f;

    const uint32_t p_off = (uint32_t)(((l & 7) + ((l >> 4) & 1) * 8) * 72 +
                                      ((l >> 3) & 1) * 8) * 2;

    auto head_pass = [&](uint32_t (*xf)[2], uint32_t pbase) {
        #pragma unroll
        for (int kk = 0; kk < 4; kk++) {
            uint32_t afr[4] = { xf[2 * kk][0], xf[2 * kk][1],
                                xf[2 * kk + 1][0], xf[2 * kk + 1][1] };
            #pragma unroll
            for (int np = 0; np < 2; np++) {
                uint32_t bq[4];
                ldsm_x4(pbase + p_off + np * (16 * 72 * 2) + kk * 32, bq);
                mma16816(y[2 * np],     afr, bq);
                mma16816(y[2 * np + 1], afr, bq + 2);
            }
        }
    };
    head_pass(xh, sb + SO_WPH);
    head_pass(xh, sb + SO_WPL);
    head_pass(xl, sb + SO_WPH);

    {
        float* outy = out + (long long)N * 64;
        int r0 = base + w * 16 + (l >> 2);
        #pragma unroll
        for (int nt = 0; nt < 4; nt++) {
            int c = nt * 8 + (l & 3) * 2;
            float q0 = y[nt][0] + bps[c];
            float q1 = y[nt][1] + bps[c + 1];
            float q2 = y[nt][2] + bps[c];
            float q3 = y[nt][3] + bps[c + 1];
            if (r0 < N)
                *reinterpret_cast<float2*>(outy + (long long)r0 * 32 + c) =
                    make_float2(q0, q1);
            if (r0 + 8 < N)
                *reinterpret_cast<float2*>(outy + (long long)(r0 + 8) * 32 + c) =
                    make_float2(q2, q3);
        }
    }
}

// ---------------------------------------------------------------------------
extern "C" void kernel_launch(void* const* d_in, const int* in_sizes, int n_in,
                              void* d_out, int out_size)
{
    const float* x  = (const float*)d_in[0];
    const float* u  = (const float*)d_in[1];
    const void*  ei = d_in[2];
    const float* W  = (const float*)d_in[3];
    const float* B  = (const float*)d_in[4];
    const float* b  = (const float*)d_in[5];
    const float* Wp = (const float*)d_in[6];
    const float* bp = (const float*)d_in[7];
    float* out = (float*)d_out;

    int N = in_sizes[0] / 64;
    int E = in_sizes[2] / 2;

    cudaFuncSetAttribute(update_kernel,
                         cudaFuncAttributeMaxDynamicSharedMemorySize, SMEM_BYTES);

    detect_idx_kernel<<<1, 32>>>(ei, E, N);
    zero_count_kernel<<<(N + 255) / 256, 256>>>(N);
    setup_weights_kernel<<<41, 256>>>(W, B, Wp, b, bp);

    hist_kernel<<<(E + 255) / 256, 256>>>(ei, E);
    scan_kernel<<<1, 1024>>>(N);
    reorder_kernel<<<(E + 255) / 256, 256>>>(ei, E);
    aggregate_kernel<<<(N + 15) / 16, 256>>>(x, N);

    int up_blocks = (N + 127) / 128;
    update_kernel<<<up_blocks, 256, SMEM_BYTES>>>(u, out, N);
}

// round 12
// speedup vs baseline: 1.8800x; 1.8800x over previous
#include <cuda_runtime.h>
#include <cuda_bf16.h>
#include <cstdint>

// ---------------------------------------------------------------------------
// RecurrentGraphNeuralNet v11: graph side = v9 atomic scatter (proven).
// Update kernel: HMMA bf16 split-precision, K SPLIT into two 64-halves with
// streamed weights (3 cp.async waves) -> smem 55.7KB -> 3 blocks/SM.
// ---------------------------------------------------------------------------

#define MAXN 100000

__device__ float g_agg[(long long)MAXN * 64];
__device__ float g_deg[MAXN];
__device__ int   g_is64;

// Weight image (per-half tiles, stride 72 bf16):
// [W0hi 9216][W0lo 9216][bs 256][bps 128][pad->18816]
// [W1hi 9216][W1lo 9216][Wph 4608][Wpl 4608]   total 46464
#define IMG_W0   0
#define IMG_BS   18432
#define IMG_BPS  18688
#define IMG_W1   18816
#define IMG_WP   37248
#define IMG_BYTES 46464
__device__ __align__(128) unsigned char g_wimg[IMG_BYTES];

// ---------------------------------------------------------------------------
__device__ __forceinline__ uint32_t smem_u32(const void* p) {
    uint32_t a;
    asm("{ .reg .u64 t; cvta.to.shared.u64 t, %1; cvt.u32.u64 %0, t; }"
        : "=r"(a) : "l"(p));
    return a;
}
__device__ __forceinline__ void ldsm_x4(uint32_t addr, uint32_t r[4]) {
    asm volatile("ldmatrix.sync.aligned.m8n8.x4.shared.b16 {%0,%1,%2,%3}, [%4];"
        : "=r"(r[0]), "=r"(r[1]), "=r"(r[2]), "=r"(r[3]) : "r"(addr));
}
__device__ __forceinline__ void mma16816(float d[4], const uint32_t a[4],
                                         const uint32_t b[2]) {
    asm volatile(
        "mma.sync.aligned.m16n8k16.row.col.f32.bf16.bf16.f32 "
        "{%0,%1,%2,%3}, {%4,%5,%6,%7}, {%8,%9}, {%0,%1,%2,%3};"
        : "+f"(d[0]), "+f"(d[1]), "+f"(d[2]), "+f"(d[3])
        : "r"(a[0]), "r"(a[1]), "r"(a[2]), "r"(a[3]), "r"(b[0]), "r"(b[1]));
}
__device__ __forceinline__ void cp_async16(uint32_t dst, const void* src) {
    asm volatile("cp.async.cg.shared.global [%0], [%1], 16;"
                 :: "r"(dst), "l"(src) : "memory");
}
__device__ __forceinline__ uint32_t pack_bf2(float lo, float hi) {
    __nv_bfloat162 h = __floats2bfloat162_rn(lo, hi);
    return *reinterpret_cast<uint32_t*>(&h);
}
__device__ __forceinline__ float bf_lo(uint32_t w) {
    __nv_bfloat16 h = *reinterpret_cast<__nv_bfloat16*>(&w);
    return __bfloat162float(h);
}
__device__ __forceinline__ float bf_hi(uint32_t w) {
    uint32_t s = w >> 16;
    __nv_bfloat16 h = *reinterpret_cast<__nv_bfloat16*>(&s);
    return __bfloat162float(h);
}

// SMEM layout (bytes): A hi/lo for CURRENT k-half (stride 72 bf16 = 144B row),
// one streamed weight slot (hi+lo), biases.
#define SO_AHI   0            // 128 x 144B = 18432
#define SO_ALO   18432        // 18432
#define SO_WHI   36864        // 9216 (also Wp hi in phase 2)
#define SO_WLO   46080        // 9216 (Wp lo lives at SO_WHI+4608)
#define SO_BS    55296        // 256
#define SO_BPS   55552        // 128
#define SMEM_BYTES 55680      // x3 blocks = 167040 <= 228KB/SM

// ---------------------------------------------------------------------------
__global__ void detect_idx_kernel(const void* ei, int E, int N) {
    if (blockIdx.x == 0 && threadIdx.x == 0) {
        const long long* p = (const long long*)ei;
        int is64 = 1;
        #pragma unroll
        for (int i = 0; i < 8; i++) {
            long long v = p[i];
            if (v < 0 || v >= (long long)N) { is64 = 0; break; }
        }
        g_is64 = is64;
    }
}

__global__ void init_kernel(long long nagg4, int n) {
    long long i = (long long)blockIdx.x * blockDim.x + threadIdx.x;
    if (i < nagg4)
        *reinterpret_cast<float4*>(g_agg + i * 4) = make_float4(0.f, 0.f, 0.f, 0.f);
    if (i < n) g_deg[i] = 0.f;
}

// per-half, transposed, hi/lo-split, ldmatrix-ready weight image (built once)
__global__ void setup_weights_kernel(
    const float* __restrict__ W, const float* __restrict__ Bm,
    const float* __restrict__ Wp, const float* __restrict__ b,
    const float* __restrict__ bp)
{
    int i = blockIdx.x * blockDim.x + threadIdx.x;
    if (i < 8192) {                       // Wt[n][k], k split in halves
        int n = i & 63, kg = i >> 6;
        float wv = (kg < 64) ? W[kg * 64 + n] : Bm[(kg - 64) * 64 + n];
        __nv_bfloat16 whi = __float2bfloat16(wv);
        __nv_bfloat16 wlo = __float2bfloat16(wv - __bfloat162float(whi));
        int half = kg >> 6, kl = kg & 63;
        uint32_t base = half ? IMG_W1 : IMG_W0;
        uint32_t off = base + (uint32_t)(n * 72 + kl) * 2;
        *reinterpret_cast<__nv_bfloat16*>(g_wimg + off)        = whi;
        *reinterpret_cast<__nv_bfloat16*>(g_wimg + off + 9216) = wlo;
    } else if (i < 10240) {               // WpT[p][k], stride 72
        int j = i - 8192;
        int p = j & 31, k = j >> 5;
        float wv = Wp[k * 32 + p];
        __nv_bfloat16 whi = __float2bfloat16(wv);
        __nv_bfloat16 wlo = __float2bfloat16(wv - __bfloat162float(whi));
        uint32_t off = IMG_WP + (uint32_t)(p * 72 + k) * 2;
        *reinterpret_cast<__nv_bfloat16*>(g_wimg + off)        = whi;
        *reinterpret_cast<__nv_bfloat16*>(g_wimg + off + 4608) = wlo;
    } else if (i < 10304) {
        int j = i - 10240;
        *reinterpret_cast<float*>(g_wimg + IMG_BS + j * 4) = b[j];
    } else if (i < 10336) {
        int j = i - 10304;
        *reinterpret_cast<float*>(g_wimg + IMG_BPS + j * 4) = bp[j];
    }
}

// ---------------------------------------------------------------------------
// Scatter (v9, proven): 4 edges/thread, batched phases, red.global.v4.
__global__ __launch_bounds__(256) void scatter_kernel(
    const float* __restrict__ x, const void* __restrict__ ei_raw, int E, int Q)
{
    long long idx = (long long)blockIdx.x * blockDim.x + threadIdx.x;
    long long total = (long long)Q * 16;
    if (idx >= total) return;

    const int is64 = g_is64;
    const int e0 = (int)(idx >> 4);
    const int f4 = ((int)idx & 15) * 4;

    int s[4], d[4];
    bool ok[4];
    #pragma unroll
    for (int j = 0; j < 4; j++) {
        int e = e0 + j * Q;
        ok[j] = (e < E);
        s[j] = 0; d[j] = 0;
        if (ok[j]) {
            if (is64) {
                const long long* ei = (const long long*)ei_raw;
                s[j] = (int)__ldg(ei + e);
                d[j] = (int)__ldg(ei + (long long)E + e);
            } else {
                const int* ei = (const int*)ei_raw;
                s[j] = __ldg(ei + e);
                d[j] = __ldg(ei + E + e);
            }
        }
    }

    float4 v[4];
    #pragma unroll
    for (int j = 0; j < 4; j++) {
        v[j] = make_float4(0.f, 0.f, 0.f, 0.f);
        if (ok[j])
            v[j] = *reinterpret_cast<const float4*>(x + (long long)s[j] * 64 + f4);
    }

    #pragma unroll
    for (int j = 0; j < 4; j++) {
        if (ok[j]) {
            float* dst = g_agg + (long long)d[j] * 64 + f4;
            asm volatile("red.global.add.v4.f32 [%0], {%1, %2, %3, %4};"
                         :: "l"(dst), "f"(v[j].x), "f"(v[j].y), "f"(v[j].z), "f"(v[j].w)
                         : "memory");
        }
    }

    if (f4 == 0) {
        #pragma unroll
        for (int j = 0; j < 4; j++)
            if (ok[j]) atomicAdd(&g_deg[d[j]], 1.0f);
    }
}

// ---------------------------------------------------------------------------
// Update v11: 128 nodes/block, 256 threads, K processed as 2 halves with
// streamed weights; 3 blocks/SM.
__global__ __launch_bounds__(256, 3) void update_kernel(
    const float* __restrict__ u, float* __restrict__ out, int N)
{
    extern __shared__ char smem[];
    const uint32_t sb = smem_u32(smem);
    const int t = threadIdx.x;
    const int l = t & 31;
    const int w = t >> 5;
    const int base = blockIdx.x * 128;

    float* bs  = (float*)(smem + SO_BS);
    float* bps = (float*)(smem + SO_BPS);

    // fragment addresses (stride 72 bf16 = 144B rows)
    const uint32_t a_off = (uint32_t)((w * 16 + (l & 15)) * 72 + (l >> 4) * 8) * 2;
    const uint32_t b_off = (uint32_t)(((l & 7) + ((l >> 4) & 1) * 8) * 72 +
                                      ((l >> 3) & 1) * 8) * 2;

    float acc[8][4];
    #pragma unroll
    for (int n = 0; n < 8; n++)
        #pragma unroll
        for (int q = 0; q < 4; q++) acc[n][q] = 0.f;

    // 4 k-tiles per half, 3 passes (hh, hl, lh)
    auto gemm_half = [&]() {
        #pragma unroll
        for (int pass = 0; pass < 3; pass++) {
            uint32_t abase = sb + ((pass == 2) ? SO_ALO : SO_AHI);
            uint32_t bbase = sb + ((pass == 1) ? SO_WLO : SO_WHI);
            #pragma unroll
            for (int kt = 0; kt < 4; kt++) {
                uint32_t af[4];
                ldsm_x4(abase + a_off + kt * 32, af);
                #pragma unroll
                for (int np = 0; np < 4; np++) {
                    uint32_t bq[4];
                    ldsm_x4(bbase + b_off + np * 2304 + kt * 32, bq);
                    mma16816(acc[2 * np],     af, bq);
                    mma16816(acc[2 * np + 1], af, bq + 2);
                }
            }
        }
    };

    // --- wave 0: W-half0 + biases (18816B) ---
    for (int i = t; i < 1176; i += 256)
        cp_async16(sb + SO_WHI + i * 16, g_wimg + IMG_W0 + i * 16);
    asm volatile("cp.async.commit_group;" ::: "memory");

    // --- stage A half0 = mean (8 chunks/thread) ---
    #pragma unroll
    for (int it = 0; it < 8; it++) {
        int i = t + it * 256;
        int node = i >> 4, ch = i & 15;
        int gn = base + node;
        float4 v = make_float4(0.f, 0.f, 0.f, 0.f);
        if (gn < N) {
            v = *reinterpret_cast<const float4*>(g_agg + (long long)gn * 64 + ch * 4);
            float inv = 1.0f / fmaxf(g_deg[gn], 1.0f);
            v.x *= inv; v.y *= inv; v.z *= inv; v.w *= inv;
        }
        uint32_t h01 = pack_bf2(v.x, v.y);
        uint32_t h23 = pack_bf2(v.z, v.w);
        uint32_t l01 = pack_bf2(v.x - bf_lo(h01), v.y - bf_hi(h01));
        uint32_t l23 = pack_bf2(v.z - bf_lo(h23), v.w - bf_hi(h23));
        uint32_t off = (uint32_t)(node * 72 + ch * 4) * 2;
        *reinterpret_cast<uint2*>(smem + SO_AHI + off) = make_uint2(h01, h23);
        *reinterpret_cast<uint2*>(smem + SO_ALO + off) = make_uint2(l01, l23);
    }
    asm volatile("cp.async.wait_group 0;" ::: "memory");
    __syncthreads();

    gemm_half();          // k in [0,64): mean @ W
    __syncthreads();

    // --- wave 1: W-half1 (18432B) ---
    for (int i = t; i < 1152; i += 256)
        cp_async16(sb + SO_WHI + i * 16, g_wimg + IMG_W1 + i * 16);
    asm volatile("cp.async.commit_group;" ::: "memory");

    // --- stage A half1 = u ---
    #pragma unroll
    for (int it = 0; it < 8; it++) {
        int i = t + it * 256;
        int node = i >> 4, ch = i & 15;
        int gn = base + node;
        float4 v = make_float4(0.f, 0.f, 0.f, 0.f);
        if (gn < N)
            v = *reinterpret_cast<const float4*>(u + (long long)gn * 64 + ch * 4);
        uint32_t h01 = pack_bf2(v.x, v.y);
        uint32_t h23 = pack_bf2(v.z, v.w);
        uint32_t l01 = pack_bf2(v.x - bf_lo(h01), v.y - bf_hi(h01));
        uint32_t l23 = pack_bf2(v.z - bf_lo(h23), v.w - bf_hi(h23));
        uint32_t off = (uint32_t)(node * 72 + ch * 4) * 2;
        *reinterpret_cast<uint2*>(smem + SO_AHI + off) = make_uint2(h01, h23);
        *reinterpret_cast<uint2*>(smem + SO_ALO + off) = make_uint2(l01, l23);
    }
    asm volatile("cp.async.wait_group 0;" ::: "memory");
    __syncthreads();

    gemm_half();          // k in [64,128): u @ B  (accumulates)
    __syncthreads();      // weight slot free for Wp

    // --- wave 2: Wp hi+lo (9216B) into the weight slot ---
    for (int i = t; i < 576; i += 256)
        cp_async16(sb + SO_WHI + i * 16, g_wimg + IMG_WP + i * 16);
    asm volatile("cp.async.commit_group;" ::: "memory");

    // --- epilogue (overlaps wave 2): bias+relu, store x_new, build frags ---
    uint32_t xh[8][2], xl[8][2];
    {
        int r0 = base + w * 16 + (l >> 2);
        #pragma unroll
        for (int n = 0; n < 8; n++) {
            int c = n * 8 + (l & 3) * 2;
            float b0 = bs[c], b1 = bs[c + 1];
            float d0 = fmaxf(acc[n][0] + b0, 0.f);
            float d1 = fmaxf(acc[n][1] + b1, 0.f);
            float d2 = fmaxf(acc[n][2] + b0, 0.f);
            float d3 = fmaxf(acc[n][3] + b1, 0.f);
            uint32_t h01 = pack_bf2(d0, d1);
            uint32_t h23 = pack_bf2(d2, d3);
            xh[n][0] = h01;
            xh[n][1] = h23;
            xl[n][0] = pack_bf2(d0 - bf_lo(h01), d1 - bf_hi(h01));
            xl[n][1] = pack_bf2(d2 - bf_lo(h23), d3 - bf_hi(h23));
            if (r0 < N)
                *reinterpret_cast<float2*>(out + (long long)r0 * 64 + c) =
                    make_float2(d0, d1);
            if (r0 + 8 < N)
                *reinterpret_cast<float2*>(out + (long long)(r0 + 8) * 64 + c) =
                    make_float2(d2, d3);
        }
    }
    asm volatile("cp.async.wait_group 0;" ::: "memory");
    __syncthreads();

    // --- head GEMM: y = x_new @ Wp (+bp), 3 passes, A-frags from regs ---
    float y[4][4];
    #pragma unroll
    for (int nt = 0; nt < 4; nt++)
        #pragma unroll
        for (int q = 0; q < 4; q++) y[nt][q] = 0.f;

    const uint32_t p_off = (uint32_t)(((l & 7) + ((l >> 4) & 1) * 8) * 72 +
                                      ((l >> 3) & 1) * 8) * 2;

    auto head_pass = [&](uint32_t (*xf)[2], uint32_t pbase) {
        #pragma unroll
        for (int kk = 0; kk < 4; kk++) {
            uint32_t afr[4] = { xf[2 * kk][0], xf[2 * kk][1],
                                xf[2 * kk + 1][0], xf[2 * kk + 1][1] };
            #pragma unroll
            for (int np = 0; np < 2; np++) {
                uint32_t bq[4];
                ldsm_x4(pbase + p_off + np * 2304 + kk * 32, bq);
                mma16816(y[2 * np],     afr, bq);
                mma16816(y[2 * np + 1], afr, bq + 2);
            }
        }
    };
    head_pass(xh, sb + SO_WHI);           // hi x Wp_hi
    head_pass(xh, sb + SO_WHI + 4608);    // hi x Wp_lo
    head_pass(xl, sb + SO_WHI);           // lo x Wp_hi

    {
        float* outy = out + (long long)N * 64;
        int r0 = base + w * 16 + (l >> 2);
        #pragma unroll
        for (int nt = 0; nt < 4; nt++) {
            int c = nt * 8 + (l & 3) * 2;
            float q0 = y[nt][0] + bps[c];
            float q1 = y[nt][1] + bps[c + 1];
            float q2 = y[nt][2] + bps[c];
            float q3 = y[nt][3] + bps[c + 1];
            if (r0 < N)
                *reinterpret_cast<float2*>(outy + (long long)r0 * 32 + c) =
                    make_float2(q0, q1);
            if (r0 + 8 < N)
                *reinterpret_cast<float2*>(outy + (long long)(r0 + 8) * 32 + c) =
                    make_float2(q2, q3);
        }
    }
}

// ---------------------------------------------------------------------------
extern "C" void kernel_launch(void* const* d_in, const int* in_sizes, int n_in,
                              void* d_out, int out_size)
{
    const float* x  = (const float*)d_in[0];
    const float* u  = (const float*)d_in[1];
    const void*  ei = d_in[2];
    const float* W  = (const float*)d_in[3];
    const float* B  = (const float*)d_in[4];
    const float* b  = (const float*)d_in[5];
    const float* Wp = (const float*)d_in[6];
    const float* bp = (const float*)d_in[7];
    float* out = (float*)d_out;

    int N = in_sizes[0] / 64;
    int E = in_sizes[2] / 2;

    cudaFuncSetAttribute(update_kernel,
                         cudaFuncAttributeMaxDynamicSharedMemorySize, SMEM_BYTES);

    detect_idx_kernel<<<1, 32>>>(ei, E, N);

    long long nagg4 = ((long long)N * 64) / 4;
    int init_blocks = (int)((nagg4 + 255) / 256);
    init_kernel<<<init_blocks, 256>>>(nagg4, N);

    setup_weights_kernel<<<41, 256>>>(W, B, Wp, b, bp);

    int Q = (E + 3) / 4;
    long long sc_threads = (long long)Q * 16;
    int sc_blocks = (int)((sc_threads + 255) / 256);
    scatter_kernel<<<sc_blocks, 256>>>(x, ei, E, Q);

    int up_blocks = (N + 127) / 128;
    update_kernel<<<up_blocks, 256, SMEM_BYTES>>>(u, out, N);
}